// round 9
// baseline (speedup 1.0000x reference)
#include <cuda_runtime.h>
#include <cstdint>

// LWTA over groups of 4 consecutive fp32 units. One float4 == one pool group.
// Keep first max (strict > matches jnp.argmax first-tie semantics), zero rest.
//
// FINAL (converged at HBM roofline): flat grid, 256 threads, block-strided
// unroll-8, 8 front-batched LDG.128 per thread; every access 512B-contiguous
// per warp. Grid=4096 exactly covers 8388608 groups.
//
// Evidence across 7 passing rounds: all flat-grid schedules sit at
// 44.7-45.5us wall / 35.5-38us kernel = 268MB mandatory traffic at
// ~7.2-7.5TB/s effective (~90-94% of 8TB/s spec; ncu's counted DRAM% omits
// the ~55MB write tail resident in L2 at profile end). Compute/issue <18%.
// Ruled out: strided-per-thread groups (L1tex 2x wavefronts, 56us),
// 512-thread blocks (per-SM L1tex queue contention, 45.5us),
// persistent grid-stride (loop overhead, 48.1us). Traffic is irreducible
// and LDG/TMA share the LTS cap, so this is the floor.

__device__ __forceinline__ float4 lwta4(float4 v) {
    float m = v.x; int idx = 0;
    if (v.y > m) { m = v.y; idx = 1; }
    if (v.z > m) { m = v.z; idx = 2; }
    if (v.w > m) { m = v.w; idx = 3; }
    float4 r;
    r.x = (idx == 0) ? v.x : 0.0f;
    r.y = (idx == 1) ? v.y : 0.0f;
    r.z = (idx == 2) ? v.z : 0.0f;
    r.w = (idx == 3) ? v.w : 0.0f;
    return r;
}

__global__ void __launch_bounds__(256) lwta_kernel(const float4* __restrict__ in,
                                                   float4* __restrict__ out,
                                                   int n_groups) {
    const int UNROLL = 8;
    const int BS = 256;
    int block_base = blockIdx.x * (BS * UNROLL);
    int tid = block_base + threadIdx.x;

    if (block_base + BS * UNROLL <= n_groups) {
        float4 v[UNROLL];
        #pragma unroll
        for (int k = 0; k < UNROLL; k++)
            v[k] = __ldcs(&in[tid + k * BS]);
        #pragma unroll
        for (int k = 0; k < UNROLL; k++)
            __stcs(&out[tid + k * BS], lwta4(v[k]));
    } else {
        #pragma unroll
        for (int k = 0; k < UNROLL; k++) {
            int i = tid + k * BS;
            if (i < n_groups)
                __stcs(&out[i], lwta4(__ldcs(&in[i])));
        }
    }
}

extern "C" void kernel_launch(void* const* d_in, const int* in_sizes, int n_in,
                              void* d_out, int out_size) {
    const float4* in = (const float4*)d_in[0];
    float4* out = (float4*)d_out;
    int n = in_sizes[0];              // 4096*8192 = 33554432 floats
    int n_groups = n / 4;             // 8388608 float4 groups
    int groups_per_block = 256 * 8;   // unroll 8
    int blocks = (n_groups + groups_per_block - 1) / groups_per_block;  // 4096
    lwta_kernel<<<blocks, 256>>>(in, out, n_groups);
}

// round 10
// speedup vs baseline: 1.0360x; 1.0360x over previous
#include <cuda_runtime.h>
#include <cstdint>

// LWTA over groups of 4 consecutive fp32 units. One float4 == one pool group.
// Keep first max (strict > matches jnp.argmax first-tie semantics), zero rest.
//
// 256-bit global access variant (sm_100a+/sm_103a: LDG.E.256 / STG.E.256 via
// ld/st.global.v8.b32). One v8 = 32B = 2 pool groups. Halves LDG/STG
// instruction count + LSU dispatch events per byte vs float4 path; DRAM
// traffic unchanged (268MB mandatory, ~35.5us floor at ~7.5TB/s effective).
// 256 threads, 2 x v8 per thread (64B), grid 8192, exact cover.

__device__ __forceinline__ void ldg256(const float* p, uint32_t* v) {
    asm volatile("ld.global.v8.b32 {%0,%1,%2,%3,%4,%5,%6,%7}, [%8];"
                 : "=r"(v[0]), "=r"(v[1]), "=r"(v[2]), "=r"(v[3]),
                   "=r"(v[4]), "=r"(v[5]), "=r"(v[6]), "=r"(v[7])
                 : "l"(p));
}

__device__ __forceinline__ void stg256(float* p, const uint32_t* v) {
    asm volatile("st.global.v8.b32 [%0], {%1,%2,%3,%4,%5,%6,%7,%8};"
                 :: "l"(p),
                    "r"(v[0]), "r"(v[1]), "r"(v[2]), "r"(v[3]),
                    "r"(v[4]), "r"(v[5]), "r"(v[6]), "r"(v[7])
                 : "memory");
}

// LWTA on one group of 4 fp32 values held as uint bits, in place.
__device__ __forceinline__ void lwta_group(uint32_t* g) {
    float f0 = __uint_as_float(g[0]);
    float f1 = __uint_as_float(g[1]);
    float f2 = __uint_as_float(g[2]);
    float f3 = __uint_as_float(g[3]);
    float m = f0; int idx = 0;
    if (f1 > m) { m = f1; idx = 1; }
    if (f2 > m) { m = f2; idx = 2; }
    if (f3 > m) { m = f3; idx = 3; }
    g[0] = (idx == 0) ? g[0] : 0u;
    g[1] = (idx == 1) ? g[1] : 0u;
    g[2] = (idx == 2) ? g[2] : 0u;
    g[3] = (idx == 3) ? g[3] : 0u;
}

__global__ void __launch_bounds__(256) lwta_kernel(const float* __restrict__ in,
                                                   float* __restrict__ out,
                                                   int n) {
    const int BS = 256;
    const int PER_BLOCK = BS * 16;               // 4096 floats per block
    int block_base = blockIdx.x * PER_BLOCK;

    if (block_base + PER_BLOCK <= n) {
        int i0 = block_base + threadIdx.x * 8;   // segment 0
        int i1 = i0 + BS * 8;                    // segment 1 (+2048 floats)
        uint32_t a[8], b[8];
        ldg256(in + i0, a);
        ldg256(in + i1, b);
        lwta_group(a);
        lwta_group(a + 4);
        lwta_group(b);
        lwta_group(b + 4);
        stg256(out + i0, a);
        stg256(out + i1, b);
    } else {
        // scalar-ish tail: per float4 group
        for (int g = block_base + threadIdx.x * 4; g + 4 <= n; g += BS * 4) {
            uint32_t v[4];
            v[0] = __float_as_uint(in[g]);
            v[1] = __float_as_uint(in[g + 1]);
            v[2] = __float_as_uint(in[g + 2]);
            v[3] = __float_as_uint(in[g + 3]);
            lwta_group(v);
            out[g]     = __uint_as_float(v[0]);
            out[g + 1] = __uint_as_float(v[1]);
            out[g + 2] = __uint_as_float(v[2]);
            out[g + 3] = __uint_as_float(v[3]);
        }
    }
}

extern "C" void kernel_launch(void* const* d_in, const int* in_sizes, int n_in,
                              void* d_out, int out_size) {
    const float* in = (const float*)d_in[0];
    float* out = (float*)d_out;
    int n = in_sizes[0];               // 4096*8192 = 33554432 floats
    int per_block = 256 * 16;          // 4096 floats per block
    int blocks = (n + per_block - 1) / per_block;  // 8192
    lwta_kernel<<<blocks, 256>>>(in, out, n);
}